// round 11
// baseline (speedup 1.0000x reference)
#include <cuda_runtime.h>
#include <cstdint>

typedef unsigned long long ull;

#define F_DIM 16
#define N_DIM 8192
#define D_DIM 64
#define K_DIM 512
#define DP    (D_DIM / 2)       // 32 d-pairs per row
#define KT    8                 // k per chunk (8 f32x2 accumulators)
#define THREADS 128             // 1 warp per SMSP
#define TILE_M 128              // rows per tile: 1 row/thread
#define TILES_PER_F 64
#define NT (F_DIM * TILES_PER_F)   // 1024 tiles
#define GRIDB 148
#define EXTRA 136               // blocks with 7 tiles (rest get 6): 136*7+12*6=1024
#define OUT_ELEMS ((size_t)F_DIM * N_DIM * D_DIM)   // 8388608

#define SMEM_W_BYTES (DP * K_DIM * sizeof(float2))   // 131072 (holds -2*w)
#define SM_WN2 SMEM_W_BYTES                          // float2 (wnorm, 0) per k: 4096
#define SM_RED (SM_WN2 + K_DIM * sizeof(float2))
#define SMEM_BYTES (SM_RED + THREADS * sizeof(float))

__device__ float g_partials[GRIDB];

// Packed fp32x2 FMA (Blackwell fma pipe: 2 fp32 MACs / instr, rt 2)
__device__ __forceinline__ ull ffma2(ull a, ull b, ull c) {
    ull d;
    asm("fma.rn.f32x2 %0, %1, %2, %3;" : "=l"(d) : "l"(a), "l"(b), "l"(c));
    return d;
}
__device__ __forceinline__ float2 u2f(ull v) {
    float2 r;
    asm("mov.b64 {%0, %1}, %2;" : "=f"(r.x), "=f"(r.y) : "l"(v));
    return r;
}

__global__ __launch_bounds__(THREADS, 1)
void vq_kernel(const float* __restrict__ x_all,
               const float* __restrict__ w_all,
               float* __restrict__ out) {
    extern __shared__ char smem[];
    float2* w2  = (float2*)smem;               // [DP][K]: (-2*w[2dp][k], -2*w[2dp+1][k])
    float2* wn2 = (float2*)(smem + SM_WN2);    // [K]: (||w_k||^2, 0)
    float*  red = (float*)(smem + SM_RED);     // [THREADS]

    const int tid = threadIdx.x;
    const int b   = blockIdx.x;

    // static contiguous tile schedule: 136 blocks x 7 tiles, 12 x 6
    const int ntile = (b < EXTRA) ? 7 : 6;
    const int t0    = (b < EXTRA) ? 7 * b : 6 * b + EXTRA;
    const int t1    = t0 + ntile;

    float loss_acc = 0.f;
    int cur_f = -1;
    const float* xg = nullptr;
    float* outf = nullptr;

    for (int t = t0; t < t1; ++t) {
        const int f = t >> 6;
        if (f != cur_f) {                       // <=2 stagings per block
            __syncthreads();
            const float* wg = w_all + (size_t)f * D_DIM * K_DIM;
            // stage -2*w repacked as d-pairs (exact scale -> bit-identical math)
            for (int i = tid; i < DP * K_DIM; i += THREADS) {
                int dp = i >> 9;
                int k  = i & (K_DIM - 1);
                float a = wg[(2 * dp) * K_DIM + k];
                float c = wg[(2 * dp + 1) * K_DIM + k];
                w2[i] = make_float2(-2.f * a, -2.f * c);
            }
            __syncthreads();
            // wn = ||w_k||^2 = 0.25 * sum((-2w)^2)  (exact rescale)
            for (int k = tid; k < K_DIM; k += THREADS) {
                float s = 0.f;
                #pragma unroll
                for (int dp = 0; dp < DP; ++dp) {
                    float2 v = w2[dp * K_DIM + k];
                    s = fmaf(v.x, v.x, s);
                    s = fmaf(v.y, v.y, s);
                }
                wn2[k] = make_float2(0.25f * s, 0.f);
            }
            __syncthreads();
            cur_f = f;
            xg   = x_all + (size_t)f * N_DIM * D_DIM;
            outf = out + (size_t)f * N_DIM * D_DIM;
        }

        const int row = (t & (TILES_PER_F - 1)) * TILE_M + tid;

        // x row in registers as natural (d, d+1) pairs
        ull x[DP];
        {
            const ulonglong2* px = (const ulonglong2*)(xg + (size_t)row * D_DIM);
            #pragma unroll
            for (int j = 0; j < DP / 2; ++j) {
                ulonglong2 v = px[j];
                x[2 * j] = v.x; x[2 * j + 1] = v.y;
            }
        }

        float best = 3.4e38f;
        int   idx  = 0;

        for (int k0 = 0; k0 < K_DIM; k0 += KT) {
            // acc[j] starts at (||w_{k0+j}||^2, 0); accumulates -2*x.w
            ull acc[KT];
            {
                const ulonglong2* ip = (const ulonglong2*)(wn2 + k0);
                #pragma unroll
                for (int j = 0; j < KT / 2; ++j) {
                    ulonglong2 v = ip[j];
                    acc[2 * j] = v.x; acc[2 * j + 1] = v.y;
                }
            }
            #pragma unroll
            for (int dp = 0; dp < DP; ++dp) {
                const ulonglong2* wp = (const ulonglong2*)(w2 + dp * K_DIM + k0);
                ull xv = x[dp];
                #pragma unroll
                for (int j = 0; j < KT / 2; ++j) {
                    ulonglong2 wv = wp[j];   // broadcast LDS.128 (one addr per warp)
                    acc[2 * j]     = ffma2(xv, wv.x, acc[2 * j]);
                    acc[2 * j + 1] = ffma2(xv, wv.y, acc[2 * j + 1]);
                }
            }
            // score = wn - 2*dot = a.x + a.y ; first-min tie-break via strict <
            #pragma unroll
            for (int j = 0; j < KT; ++j) {
                float2 a = u2f(acc[j]);
                float s = a.x + a.y;
                if (s < best) { best = s; idx = k0 + j; }
            }
        }

        // gather winner (w2 holds -2w -> scale by -0.5, exact), write + loss
        {
            float4* o4 = (float4*)(outf + (size_t)row * D_DIM);
            #pragma unroll
            for (int j = 0; j < DP / 2; ++j) {
                float2 m0 = w2[(2 * j) * K_DIM + idx];
                float2 m1 = w2[(2 * j + 1) * K_DIM + idx];
                float q0x = -0.5f * m0.x, q0y = -0.5f * m0.y;
                float q1x = -0.5f * m1.x, q1y = -0.5f * m1.y;
                float2 v0 = u2f(x[2 * j]), v1 = u2f(x[2 * j + 1]);
                float d;
                d = q0x - v0.x; loss_acc = fmaf(d, d, loss_acc);
                d = q0y - v0.y; loss_acc = fmaf(d, d, loss_acc);
                d = q1x - v1.x; loss_acc = fmaf(d, d, loss_acc);
                d = q1y - v1.y; loss_acc = fmaf(d, d, loss_acc);
                o4[j] = make_float4(q0x, q0y, q1x, q1y);
            }
        }
    }

    // deterministic block reduction of loss partial
    __syncthreads();
    red[tid] = loss_acc;
    __syncthreads();
    #pragma unroll
    for (int s = THREADS / 2; s > 0; s >>= 1) {
        if (tid < s) red[tid] += red[tid + s];
        __syncthreads();
    }
    if (tid == 0) g_partials[b] = red[0];
}

__global__ void vq_finalize(float* out, int write_loss) {
    __shared__ float red[256];
    int t = threadIdx.x;
    red[t] = (t < GRIDB) ? g_partials[t] : 0.f;
    __syncthreads();
    #pragma unroll
    for (int s = 128; s > 0; s >>= 1) {
        if (t < s) red[t] += red[t + s];
        __syncthreads();
    }
    if (t == 0 && write_loss) {
        // loss = q_latent + 0.25 * e_latent = 1.25 * mean((q - x)^2)
        out[OUT_ELEMS] = 1.25f * red[0] / (float)OUT_ELEMS;
    }
}

extern "C" void kernel_launch(void* const* d_in, const int* in_sizes, int n_in,
                              void* d_out, int out_size) {
    const float* x = (const float*)d_in[0];
    const float* w = (const float*)d_in[1];
    float* out = (float*)d_out;

    cudaFuncSetAttribute(vq_kernel, cudaFuncAttributeMaxDynamicSharedMemorySize,
                         (int)SMEM_BYTES);
    vq_kernel<<<GRIDB, THREADS, SMEM_BYTES>>>(x, w, out);

    int write_loss = (out_size > (int)OUT_ELEMS) ? 1 : 0;
    vq_finalize<<<1, 256>>>(out, write_loss);
}

// round 12
// speedup vs baseline: 1.0068x; 1.0068x over previous
#include <cuda_runtime.h>
#include <cstdint>

typedef unsigned long long ull;

#define F_DIM 16
#define N_DIM 8192
#define D_DIM 64
#define K_DIM 512
#define KH    256               // codes per thread (half the codebook)
#define DP    (D_DIM / 2)       // 32 d-pairs per row
#define DPH   (DP / 2)          // 16 d-pairs written per thread (output split)
#define KT    8                 // k per chunk (8 f32x2 accumulators)
#define THREADS 256             // 2 warps per SMSP (latency cover)
#define TILE_M 128              // rows per tile: 2 threads per row (k-split)
#define TILES_PER_F 64
#define GRIDB 148
#define EXTRA 136               // 136 blocks x 7 tiles + 12 x 6 = 1024 tiles
#define OUT_ELEMS ((size_t)F_DIM * N_DIM * D_DIM)   // 8388608

// ---- smem layout: half-B regions staggered +16B so even/odd lanes hit
// ---- disjoint bank groups (region gap 65552 % 128 == 16 -> +4 banks).
#define SM_WA 0
#define SM_WB (SM_WA + DP * KH * 8 + 16)          // 65552
#define SM_NA (SM_WB + DP * KH * 8 + 16)          // 131120
#define SM_NB (SM_NA + KH * 8 + 16)               // 133184  (gap 2064 % 128 == 16)
#define SM_RED (SM_NB + KH * 8 + 16)
#define SMEM_BYTES (SM_RED + THREADS * 4)         // ~136 KB

__device__ float g_partials[GRIDB];

// Packed fp32x2 FMA (Blackwell fma pipe: 2 fp32 MACs / instr, rt 2)
__device__ __forceinline__ ull ffma2(ull a, ull b, ull c) {
    ull d;
    asm("fma.rn.f32x2 %0, %1, %2, %3;" : "=l"(d) : "l"(a), "l"(b), "l"(c));
    return d;
}
__device__ __forceinline__ float2 u2f(ull v) {
    float2 r;
    asm("mov.b64 {%0, %1}, %2;" : "=f"(r.x), "=f"(r.y) : "l"(v));
    return r;
}

__global__ __launch_bounds__(THREADS, 1)
void vq_kernel(const float* __restrict__ x_all,
               const float* __restrict__ w_all,
               float* __restrict__ out) {
    extern __shared__ char smem[];
    float* red = (float*)(smem + SM_RED);

    const int tid  = threadIdx.x;
    const int b    = blockIdx.x;
    const int half = tid & 1;            // which 256-code half this thread scores
    const int rloc = tid >> 1;           // row within tile

    // this thread's staggered regions
    char* wbase = smem + (half ? SM_WB : SM_WA);          // [DP][KH] float2 = -2*w
    const float2* wn2 = (const float2*)(smem + (half ? SM_NB : SM_NA));  // (||w||^2, 0)

    // static contiguous tile schedule: 136 blocks x 7 tiles, 12 x 6
    const int ntile = (b < EXTRA) ? 7 : 6;
    const int t0    = (b < EXTRA) ? 7 * b : 6 * b + EXTRA;
    const int t1    = t0 + ntile;

    float loss_acc = 0.f;
    int cur_f = -1;
    const float* xg = nullptr;
    float* outf = nullptr;

    for (int t = t0; t < t1; ++t) {
        const int f = t >> 6;
        if (f != cur_f) {                                 // <=2 stagings per block
            __syncthreads();
            const float* wg = w_all + (size_t)f * D_DIM * K_DIM;
            // stage both halves: region h holds -2*w for k in [256h, 256h+256)
            for (int h = 0; h < 2; ++h) {
                float2* w2 = (float2*)(smem + (h ? SM_WB : SM_WA));
                for (int i = tid; i < DP * KH; i += THREADS) {
                    int dp = i >> 8;                       // / KH
                    int j  = i & (KH - 1);
                    int k  = h * KH + j;
                    float a = wg[(2 * dp) * K_DIM + k];
                    float c = wg[(2 * dp + 1) * K_DIM + k];
                    w2[i] = make_float2(-2.f * a, -2.f * c);
                }
            }
            __syncthreads();
            // norm tables: wn = 0.25 * sum((-2w)^2) (exact rescale)
            for (int i = tid; i < 2 * KH; i += THREADS) {
                int h = i >> 8, j = i & (KH - 1);
                const float2* w2 = (const float2*)(smem + (h ? SM_WB : SM_WA));
                float s = 0.f;
                #pragma unroll
                for (int dp = 0; dp < DP; ++dp) {
                    float2 v = w2[dp * KH + j];
                    s = fmaf(v.x, v.x, s);
                    s = fmaf(v.y, v.y, s);
                }
                ((float2*)(smem + (h ? SM_NB : SM_NA)))[j] = make_float2(0.25f * s, 0.f);
            }
            __syncthreads();
            cur_f = f;
            xg   = x_all + (size_t)f * N_DIM * D_DIM;
            outf = out + (size_t)f * N_DIM * D_DIM;
        }

        const int row = (t & (TILES_PER_F - 1)) * TILE_M + rloc;

        // full x row in registers as natural (d, d+1) pairs (pair shares the row)
        ull x[DP];
        {
            const ulonglong2* px = (const ulonglong2*)(xg + (size_t)row * D_DIM);
            #pragma unroll
            for (int j = 0; j < DP / 2; ++j) {
                ulonglong2 v = px[j];
                x[2 * j] = v.x; x[2 * j + 1] = v.y;
            }
        }

        float best = 3.4e38f;
        int   idx  = 0;                   // local index within my half

        for (int k0 = 0; k0 < KH; k0 += KT) {
            // acc[j] starts at (||w_{k0+j}||^2, 0); accumulates -2*x.w
            ull acc[KT];
            {
                const ulonglong2* ip = (const ulonglong2*)(wn2 + k0);
                #pragma unroll
                for (int j = 0; j < KT / 2; ++j) {
                    ulonglong2 v = ip[j];
                    acc[2 * j] = v.x; acc[2 * j + 1] = v.y;
                }
            }
            #pragma unroll
            for (int dp = 0; dp < DP; ++dp) {
                const ulonglong2* wp = (const ulonglong2*)(wbase + (dp * KH + k0) * 8);
                ull xv = x[dp];
                #pragma unroll
                for (int j = 0; j < KT / 2; ++j) {
                    ulonglong2 wv = wp[j];   // 16-lane broadcast per bank group
                    acc[2 * j]     = ffma2(xv, wv.x, acc[2 * j]);
                    acc[2 * j + 1] = ffma2(xv, wv.y, acc[2 * j + 1]);
                }
            }
            // score = ||w||^2 - 2*dot = a.x + a.y ; first-min via strict <
            #pragma unroll
            for (int j = 0; j < KT; ++j) {
                float2 a = u2f(acc[j]);
                float s = a.x + a.y;
                if (s < best) { best = s; idx = k0 + j; }
            }
        }

        // combine across the lane pair (one shfl per row); ties -> lower k
        int kg = half * KH + idx;
        {
            float os = __shfl_xor_sync(0xffffffffu, best, 1);
            int   ok = __shfl_xor_sync(0xffffffffu, kg, 1);
            if (os < best || (os == best && ok < kg)) { best = os; kg = ok; }
        }

        // write my d-half of the winner (w2 holds -2w -> scale -0.5, exact) + loss
        {
            const float2* wr = (const float2*)(smem + ((kg < KH) ? SM_WA : SM_WB))
                               + (kg & (KH - 1));
            float4* o4 = (float4*)(outf + (size_t)row * D_DIM + half * (D_DIM / 2));
            #pragma unroll
            for (int j = 0; j < DPH / 2; ++j) {
                int dp0 = half * DPH + 2 * j;
                float2 m0 = wr[dp0 * KH];
                float2 m1 = wr[(dp0 + 1) * KH];
                float q0x = -0.5f * m0.x, q0y = -0.5f * m0.y;
                float q1x = -0.5f * m1.x, q1y = -0.5f * m1.y;
                float2 v0 = u2f(x[dp0]), v1 = u2f(x[dp0 + 1]);
                float d;
                d = q0x - v0.x; loss_acc = fmaf(d, d, loss_acc);
                d = q0y - v0.y; loss_acc = fmaf(d, d, loss_acc);
                d = q1x - v1.x; loss_acc = fmaf(d, d, loss_acc);
                d = q1y - v1.y; loss_acc = fmaf(d, d, loss_acc);
                o4[j] = make_float4(q0x, q0y, q1x, q1y);
            }
        }
    }

    // deterministic block reduction of loss partial
    __syncthreads();
    red[tid] = loss_acc;
    __syncthreads();
    #pragma unroll
    for (int s = THREADS / 2; s > 0; s >>= 1) {
        if (tid < s) red[tid] += red[tid + s];
        __syncthreads();
    }
    if (tid == 0) g_partials[b] = red[0];
}

__global__ void vq_finalize(float* out, int write_loss) {
    __shared__ float red[256];
    int t = threadIdx.x;
    red[t] = (t < GRIDB) ? g_partials[t] : 0.f;
    __syncthreads();
    #pragma unroll
    for (int s = 128; s > 0; s >>= 1) {
        if (t < s) red[t] += red[t + s];
        __syncthreads();
    }
    if (t == 0 && write_loss) {
        // loss = q_latent + 0.25 * e_latent = 1.25 * mean((q - x)^2)
        out[OUT_ELEMS] = 1.25f * red[0] / (float)OUT_ELEMS;
    }
}

extern "C" void kernel_launch(void* const* d_in, const int* in_sizes, int n_in,
                              void* d_out, int out_size) {
    const float* x = (const float*)d_in[0];
    const float* w = (const float*)d_in[1];
    float* out = (float*)d_out;

    cudaFuncSetAttribute(vq_kernel, cudaFuncAttributeMaxDynamicSharedMemorySize,
                         (int)SMEM_BYTES);
    vq_kernel<<<GRIDB, THREADS, SMEM_BYTES>>>(x, w, out);

    int write_loss = (out_size > (int)OUT_ELEMS) ? 1 : 0;
    vq_finalize<<<1, 256>>>(out, write_loss);
}